// round 2
// baseline (speedup 1.0000x reference)
#include <cuda_runtime.h>
#include <math.h>

#define B_  128
#define T_  512
#define NI  64
#define NH  1024
#define NO  64
#define BK  32

// Scratch (allocation-free rule: __device__ globals)
__device__ float g_enc[(size_t)T_ * B_ * NH];   // 256 MB, encoder projection [t][b][h]
__device__ float g_h[2][B_ * NH];               // ping-pong hidden state [b][h]

// ---------------------------------------------------------------------------
// hidden0[b][h] = hinit_w[h] + hinit_b[h]
// ---------------------------------------------------------------------------
__global__ void init_hidden_kernel(const float* __restrict__ hinit_w,
                                   const float* __restrict__ hinit_b) {
    int idx = blockIdx.x * blockDim.x + threadIdx.x;
    if (idx < B_ * NH) {
        int h = idx & (NH - 1);
        g_h[0][idx] = hinit_w[h] + hinit_b[h];
    }
}

// ---------------------------------------------------------------------------
// Encoder GEMM: g_enc[t][b][h] = dot(x[b][t][:], enc_w[h][:]) + enc_b[h]
// Block tile: 32 (t,b)-rows x 64 h, K=64. 256 threads, thread tile 4r x 2h.
// ---------------------------------------------------------------------------
__global__ void __launch_bounds__(256) enc_kernel(const float* __restrict__ x,
                                                  const float* __restrict__ enc_w,
                                                  const float* __restrict__ enc_b) {
    __shared__ float xs[32][NI + 1];
    __shared__ float ws[64][NI + 1];
    const int tid = threadIdx.x;
    const int tb0 = blockIdx.x * 32;   // 2048 tiles
    const int h0  = blockIdx.y * 64;   // 16 tiles

    for (int i = tid; i < 32 * NI; i += 256) {
        int r = i >> 6, c = i & 63;
        int tb = tb0 + r;
        int t = tb >> 7, b = tb & 127;
        xs[r][c] = x[(size_t)b * (T_ * NI) + t * NI + c];
    }
    for (int i = tid; i < 64 * NI; i += 256) {
        int r = i >> 6, c = i & 63;
        ws[r][c] = enc_w[(h0 + r) * NI + c];
    }
    __syncthreads();

    const int rg = tid & 7;    // 8 row-groups of 4 rows
    const int hg = tid >> 3;   // 32 h-groups of 2 h
    float acc[4][2] = {};
#pragma unroll
    for (int k = 0; k < NI; k++) {
        float w0 = ws[hg * 2 + 0][k];
        float w1 = ws[hg * 2 + 1][k];
#pragma unroll
        for (int j = 0; j < 4; j++) {
            float xv = xs[rg * 4 + j][k];
            acc[j][0] += xv * w0;
            acc[j][1] += xv * w1;
        }
    }
#pragma unroll
    for (int j = 0; j < 4; j++) {
        int tb = tb0 + rg * 4 + j;
#pragma unroll
        for (int q = 0; q < 2; q++) {
            int h = h0 + hg * 2 + q;
            g_enc[(size_t)tb * NH + h] = acc[j][q] + enc_b[h];
        }
    }
}

// ---------------------------------------------------------------------------
// Shared decode GEMM block: out[b][o0..o0+7] = dot(hin[b,:], dec_w[o,:]) + dec_b[o]
// 128 threads, thread tile 4b x 2o.
// ---------------------------------------------------------------------------
__device__ __forceinline__ void dec_block(const float* __restrict__ hin,
                                          const float* __restrict__ dec_w,
                                          const float* __restrict__ dec_b,
                                          float* __restrict__ outp, int o_tile) {
    __shared__ float dhs[128][BK + 1];
    __shared__ float dws[8][BK + 1];
    const int tid = threadIdx.x;
    const int o0 = o_tile * 8;
    const int hg = tid & 3;    // 4 o-groups of 2
    const int bg = tid >> 2;   // 32 b-groups of 4
    float acc[4][2] = {};

    for (int k0 = 0; k0 < NH; k0 += BK) {
#pragma unroll
        for (int n = 0; n < 32; n++) {
            int i = n * 128 + tid;
            int b = i >> 5, kk = i & 31;
            dhs[b][kk] = hin[b * NH + k0 + kk];
        }
#pragma unroll
        for (int n = 0; n < 2; n++) {
            int i = n * 128 + tid;
            int r = i >> 5, kk = i & 31;
            dws[r][kk] = dec_w[(o0 + r) * NH + k0 + kk];
        }
        __syncthreads();
#pragma unroll
        for (int kk = 0; kk < BK; kk++) {
            float w0 = dws[hg * 2 + 0][kk];
            float w1 = dws[hg * 2 + 1][kk];
#pragma unroll
            for (int j = 0; j < 4; j++) {
                float hv = dhs[bg * 4 + j][kk];
                acc[j][0] += hv * w0;
                acc[j][1] += hv * w1;
            }
        }
        __syncthreads();
    }
#pragma unroll
    for (int j = 0; j < 4; j++) {
        int b = bg * 4 + j;
#pragma unroll
        for (int q = 0; q < 2; q++) {
            int o = o0 + hg * 2 + q;
            outp[b * NO + o] = acc[j][q] + dec_b[o];
        }
    }
}

// ---------------------------------------------------------------------------
// One recurrent step t:
//   blocks 0..127 : 8 h-cols each; compute accR = h@rec_w^T, accF = h@fgt_w^T,
//                   f = sigmoid(accF), hnew = softsign(enc[t]+accR),
//                   h_out = (1-f)*h + f*hnew
//   blocks 128..135: decode PREVIOUS hidden (hin) -> out[t-1]   (skip at t==0)
// ---------------------------------------------------------------------------
__global__ void __launch_bounds__(128) step_kernel(const float* __restrict__ rec_w,
                                                   const float* __restrict__ fgt_w,
                                                   const float* __restrict__ dec_w,
                                                   const float* __restrict__ dec_b,
                                                   float* __restrict__ out,
                                                   int t) {
    const float* __restrict__ hin = g_h[t & 1];
    float* __restrict__ hout = g_h[(t + 1) & 1];
    const int bid = blockIdx.x;
    const int tid = threadIdx.x;

    if (bid < 128) {
        __shared__ float hs[128][BK + 1];
        __shared__ float wrs[8][BK + 1];
        __shared__ float wfs[8][BK + 1];
        const int h0 = bid * 8;
        const int hg = tid & 3;    // 4 h-groups of 2
        const int bg = tid >> 2;   // 32 b-groups of 4
        float accR[4][2] = {};
        float accF[4][2] = {};

        for (int k0 = 0; k0 < NH; k0 += BK) {
#pragma unroll
            for (int n = 0; n < 32; n++) {
                int i = n * 128 + tid;
                int b = i >> 5, kk = i & 31;
                hs[b][kk] = hin[b * NH + k0 + kk];
            }
#pragma unroll
            for (int n = 0; n < 2; n++) {
                int i = n * 128 + tid;
                int r = i >> 5, kk = i & 31;
                wrs[r][kk] = rec_w[(h0 + r) * NH + k0 + kk];
                wfs[r][kk] = fgt_w[(h0 + r) * NH + k0 + kk];
            }
            __syncthreads();
#pragma unroll
            for (int kk = 0; kk < BK; kk++) {
                float wr0 = wrs[hg * 2 + 0][kk];
                float wr1 = wrs[hg * 2 + 1][kk];
                float wf0 = wfs[hg * 2 + 0][kk];
                float wf1 = wfs[hg * 2 + 1][kk];
#pragma unroll
                for (int j = 0; j < 4; j++) {
                    float hv = hs[bg * 4 + j][kk];
                    accR[j][0] += hv * wr0;
                    accR[j][1] += hv * wr1;
                    accF[j][0] += hv * wf0;
                    accF[j][1] += hv * wf1;
                }
            }
            __syncthreads();
        }

        const float* enc_t = g_enc + (size_t)t * B_ * NH;
#pragma unroll
        for (int j = 0; j < 4; j++) {
            int b = bg * 4 + j;
#pragma unroll
            for (int q = 0; q < 2; q++) {
                int h = h0 + hg * 2 + q;
                float f = 1.0f / (1.0f + expf(-accF[j][q]));
                float hold = hin[b * NH + h];
                float s = enc_t[b * NH + h] + accR[j][q];
                float hnew = s / (1.0f + fabsf(s));
                hout[b * NH + h] = (1.0f - f) * hold + f * hnew;
            }
        }
    } else {
        if (t == 0) return;
        float* outp = out + (size_t)(t - 1) * B_ * NO;
        dec_block(hin, dec_w, dec_b, outp, bid - 128);
    }
}

// ---------------------------------------------------------------------------
// Final: decode last hidden -> out[T-1]; copy hidden -> d_out tail
// Final hidden lives in g_h[0] (T=512 is even).
// ---------------------------------------------------------------------------
__global__ void __launch_bounds__(128) final_kernel(const float* __restrict__ dec_w,
                                                    const float* __restrict__ dec_b,
                                                    float* __restrict__ out,
                                                    int writeHidden) {
    const float* __restrict__ hin = g_h[0];
    const int bid = blockIdx.x;
    const int tid = threadIdx.x;
    if (bid < 8) {
        float* outp = out + (size_t)(T_ - 1) * B_ * NO;
        dec_block(hin, dec_w, dec_b, outp, bid);
    } else {
        if (!writeHidden) return;
        float* hid_out = out + (size_t)T_ * B_ * NO;
        int base = (bid - 8) * (B_ * NH / 8);
        for (int i = tid; i < B_ * NH / 8; i += 128)
            hid_out[base + i] = hin[base + i];
    }
}

// ---------------------------------------------------------------------------
extern "C" void kernel_launch(void* const* d_in, const int* in_sizes, int n_in,
                              void* d_out, int out_size) {
    const float* x       = (const float*)d_in[0];
    const float* enc_w   = (const float*)d_in[1];
    const float* enc_b   = (const float*)d_in[2];
    const float* rec_w   = (const float*)d_in[3];
    const float* fgt_w   = (const float*)d_in[4];
    const float* dec_w   = (const float*)d_in[5];
    const float* dec_b   = (const float*)d_in[6];
    const float* hinit_w = (const float*)d_in[7];
    const float* hinit_b = (const float*)d_in[8];
    float* out = (float*)d_out;

    init_hidden_kernel<<<(B_ * NH + 255) / 256, 256>>>(hinit_w, hinit_b);

    dim3 eg(T_ * B_ / 32, NH / 64);
    enc_kernel<<<eg, 256>>>(x, enc_w, enc_b);

    for (int t = 0; t < T_; t++)
        step_kernel<<<136, 128>>>(rec_w, fgt_w, dec_w, dec_b, out, t);

    int writeHidden = (out_size >= T_ * B_ * NO + B_ * NH) ? 1 : 0;
    final_kernel<<<16, 128>>>(dec_w, dec_b, out, writeHidden);
}

// round 3
// speedup vs baseline: 1.0802x; 1.0802x over previous
#include <cuda_runtime.h>
#include <math.h>

#define B_   128
#define T_   512
#define NI   64
#define NH   1024
#define NO   64

#define NCTA    264          // 66 j-blocks * 2 b-split * 2 k-split
#define NTHR    128
#define NTOT    (NCTA*NTHR)  // 33792
#define KHALF   512
#define BK      32           // k-chunk
#define NCHUNK  (KHALF/BK)   // 16
#define JTILE   16           // column-pairs per CTA
#define NPAIRS  1056         // 1024 rec/fgt pairs + 32 dec pairs
#define SMEM_BYTES ((512*JTILE + 2*BK*64) * 8)   // ws 64KB + hs 32KB = 98304

// ---------------- scratch (device globals; no allocation allowed) -----------
__device__ float g_enc[(size_t)T_ * B_ * NH];          // encoder proj [t][b][h]
__device__ float g_hid[2][B_ * NH];                    // ping-pong hidden
__device__ unsigned long long g_part[2ull * B_ * NPAIRS]; // partials (accR,accF) pairs
__device__ volatile unsigned g_gen;
__device__ unsigned g_cnt;

// ---------------- helpers ----------------------------------------------------
__device__ __forceinline__ float f2lo(unsigned long long v) { return __uint_as_float((unsigned)v); }
__device__ __forceinline__ float f2hi(unsigned long long v) { return __uint_as_float((unsigned)(v >> 32)); }
#define FMA2(d, a, b) asm("fma.rn.f32x2 %0, %1, %2, %0;" : "+l"(d) : "l"(a), "l"(b))

__device__ __forceinline__ unsigned long long ldcg_u64(const unsigned long long* p) {
    return __double_as_longlong(__ldcg((const double*)p));
}
__device__ __forceinline__ void stcg_u64(unsigned long long* p, unsigned long long v) {
    __stcg((double*)p, __longlong_as_double(v));
}

__device__ __forceinline__ void grid_barrier() {
    __syncthreads();
    __threadfence();
    if (threadIdx.x == 0) {
        unsigned gen = g_gen;
        if (atomicAdd(&g_cnt, 1) == NCTA - 1) {
            atomicExch(&g_cnt, 0);
            __threadfence();
            g_gen = gen + 1;
        } else {
            while (g_gen == gen) { }
        }
    }
    __syncthreads();
}

// ---------------- hidden0[b][h] = hinit_w[h] + hinit_b[h] -------------------
__global__ void init_hidden_kernel(const float* __restrict__ hinit_w,
                                   const float* __restrict__ hinit_b) {
    int idx = blockIdx.x * blockDim.x + threadIdx.x;
    if (idx < B_ * NH) {
        int h = idx & (NH - 1);
        g_hid[0][idx] = hinit_w[h] + hinit_b[h];
    }
}

// ---------------- encoder GEMM (one-shot, off the critical path) ------------
__global__ void __launch_bounds__(256) enc_kernel(const float* __restrict__ x,
                                                  const float* __restrict__ enc_w,
                                                  const float* __restrict__ enc_b) {
    __shared__ float xs[32][NI + 1];
    __shared__ float ws[64][NI + 1];
    const int tid = threadIdx.x;
    const int tb0 = blockIdx.x * 32;
    const int h0  = blockIdx.y * 64;

    for (int i = tid; i < 32 * NI; i += 256) {
        int r = i >> 6, c = i & 63;
        int tb = tb0 + r;
        int t = tb >> 7, b = tb & 127;
        xs[r][c] = x[(size_t)b * (T_ * NI) + t * NI + c];
    }
    for (int i = tid; i < 64 * NI; i += 256) {
        int r = i >> 6, c = i & 63;
        ws[r][c] = enc_w[(h0 + r) * NI + c];
    }
    __syncthreads();

    const int rg = tid & 7;
    const int hg = tid >> 3;
    float acc[4][2] = {};
#pragma unroll
    for (int k = 0; k < NI; k++) {
        float w0 = ws[hg * 2 + 0][k];
        float w1 = ws[hg * 2 + 1][k];
#pragma unroll
        for (int j = 0; j < 4; j++) {
            float xv = xs[rg * 4 + j][k];
            acc[j][0] += xv * w0;
            acc[j][1] += xv * w1;
        }
    }
#pragma unroll
    for (int j = 0; j < 4; j++) {
        int tb = tb0 + rg * 4 + j;
#pragma unroll
        for (int q = 0; q < 2; q++) {
            int h = h0 + hg * 2 + q;
            g_enc[(size_t)tb * NH + h] = acc[j][q] + enc_b[h];
        }
    }
}

// ---------------- persistent recurrent kernel --------------------------------
// CTA role: kh = bid&1 (k-half), bs = (bid>>1)&1 (b-half), jb = bid>>2 (0..65).
// Column pair j: j<1024 -> (rec_w[j], fgt_w[j]) ; j>=1024 -> (dec_w[2(j-1024)], dec_w[2(j-1024)+1])
__global__ void __launch_bounds__(NTHR) persist_kernel(const float* __restrict__ rec_w,
                                                       const float* __restrict__ fgt_w,
                                                       const float* __restrict__ dec_w,
                                                       const float* __restrict__ dec_b,
                                                       float* __restrict__ out,
                                                       int writeHidden) {
    extern __shared__ float smem[];
    float2* ws = (float2*)smem;                    // [512][16] pairs
    float2* hsb = (float2*)(smem + 512 * JTILE * 2); // [2][BK][64] dup'd hidden

    const int tid = threadIdx.x;
    const int bid = blockIdx.x;
    const int kh  = bid & 1;
    const int bs  = (bid >> 1) & 1;
    const int jb  = bid >> 2;
    const int j0  = jb * JTILE;
    const int b0  = bs * 64;
    const int gid = bid * NTHR + tid;

    const int hg = tid & 7;     // 8 j-groups of 2 pairs
    const int bg = tid >> 3;    // 16 b-groups of 4 rows

    // ---- load weight slice into SMEM once (interleaved pairs) ----
    for (int i = tid; i < 512 * JTILE; i += NTHR) {
        int k = i >> 4, jj = i & 15;
        int j = j0 + jj;
        int gk = kh * KHALF + k;
        float a, b;
        if (j < 1024) { a = rec_w[j * NH + gk]; b = fgt_w[j * NH + gk]; }
        else { int o = (j - 1024) * 2; a = dec_w[o * NH + gk]; b = dec_w[(o + 1) * NH + gk]; }
        ws[k * JTILE + jj] = make_float2(a, b);
    }
    __syncthreads();

    for (int t = 0; t <= T_; t++) {
        const float* __restrict__ hin = g_hid[t & 1];
        // ================= GEMM phase =================
        if (t < T_ || j0 >= 1024) {
            float4 r[4];
            // prefetch chunk 0
#pragma unroll
            for (int s = 0; s < 4; s++) {
                int slot = s * NTHR + tid;
                int b = slot >> 3, kg = slot & 7;
                r[s] = __ldcg((const float4*)(hin + (b0 + b) * NH + kh * KHALF + kg * 4));
            }
            {
                float2* hb = hsb;
#pragma unroll
                for (int s = 0; s < 4; s++) {
                    int slot = s * NTHR + tid;
                    int b = slot >> 3, kg = slot & 7;
                    hb[(kg * 4 + 0) * 64 + b] = make_float2(r[s].x, r[s].x);
                    hb[(kg * 4 + 1) * 64 + b] = make_float2(r[s].y, r[s].y);
                    hb[(kg * 4 + 2) * 64 + b] = make_float2(r[s].z, r[s].z);
                    hb[(kg * 4 + 3) * 64 + b] = make_float2(r[s].w, r[s].w);
                }
            }
            __syncthreads();

            unsigned long long acc[4][2] = {};
            for (int kc = 0; kc < NCHUNK; kc++) {
                if (kc + 1 < NCHUNK) {
#pragma unroll
                    for (int s = 0; s < 4; s++) {
                        int slot = s * NTHR + tid;
                        int b = slot >> 3, kg = slot & 7;
                        r[s] = __ldcg((const float4*)(hin + (b0 + b) * NH + kh * KHALF +
                                                      (kc + 1) * BK + kg * 4));
                    }
                }
                const float2* hb = hsb + (kc & 1) * (BK * 64);
#pragma unroll
                for (int kk = 0; kk < BK; kk++) {
                    ulonglong2 ha = *(const ulonglong2*)(hb + kk * 64 + bg * 4);
                    ulonglong2 hc = *(const ulonglong2*)(hb + kk * 64 + bg * 4 + 2);
                    ulonglong2 wv = *(const ulonglong2*)(ws + (kc * BK + kk) * JTILE + hg * 2);
                    FMA2(acc[0][0], ha.x, wv.x); FMA2(acc[0][1], ha.x, wv.y);
                    FMA2(acc[1][0], ha.y, wv.x); FMA2(acc[1][1], ha.y, wv.y);
                    FMA2(acc[2][0], hc.x, wv.x); FMA2(acc[2][1], hc.x, wv.y);
                    FMA2(acc[3][0], hc.y, wv.x); FMA2(acc[3][1], hc.y, wv.y);
                }
                if (kc + 1 < NCHUNK) {
                    __syncthreads();
                    float2* hb2 = hsb + ((kc + 1) & 1) * (BK * 64);
#pragma unroll
                    for (int s = 0; s < 4; s++) {
                        int slot = s * NTHR + tid;
                        int b = slot >> 3, kg = slot & 7;
                        hb2[(kg * 4 + 0) * 64 + b] = make_float2(r[s].x, r[s].x);
                        hb2[(kg * 4 + 1) * 64 + b] = make_float2(r[s].y, r[s].y);
                        hb2[(kg * 4 + 2) * 64 + b] = make_float2(r[s].z, r[s].z);
                        hb2[(kg * 4 + 3) * 64 + b] = make_float2(r[s].w, r[s].w);
                    }
                    __syncthreads();
                }
            }
            // write partial pairs to gmem
            unsigned long long* pp = g_part + ((size_t)kh * B_ + b0 + bg * 4) * NPAIRS + j0 + hg * 2;
#pragma unroll
            for (int ib = 0; ib < 4; ib++) {
#pragma unroll
                for (int jh = 0; jh < 2; jh++)
                    stcg_u64(pp + (size_t)ib * NPAIRS + jh, acc[ib][jh]);
            }
        }
        grid_barrier();

        // ================= epilogue phase =================
        const float* __restrict__ hinE = g_hid[t & 1];
        float* __restrict__ houtE = g_hid[(t + 1) & 1];
        if (t < T_) {
            for (int i = gid; i < B_ * NH; i += NTOT) {
                int b = i >> 10, j = i & (NH - 1);
                unsigned long long p0 = ldcg_u64(g_part + (size_t)b * NPAIRS + j);
                unsigned long long p1 = ldcg_u64(g_part + (size_t)(B_ + b) * NPAIRS + j);
                float accR = f2lo(p0) + f2lo(p1);
                float accF = f2hi(p0) + f2hi(p1);
                float f = 1.0f / (1.0f + expf(-accF));
                float s = __ldcg(g_enc + ((size_t)t << 17) + i) + accR;
                float hnew = s / (1.0f + fabsf(s));
                float hold = __ldcg(hinE + i);
                __stcg(houtE + i, (1.0f - f) * hold + f * hnew);
            }
        }
        if (t >= 1) {
            for (int i = gid; i < B_ * 32; i += NTOT) {
                int b = i >> 5, jj = i & 31;
                unsigned long long p0 = ldcg_u64(g_part + (size_t)b * NPAIRS + 1024 + jj);
                unsigned long long p1 = ldcg_u64(g_part + (size_t)(B_ + b) * NPAIRS + 1024 + jj);
                float v0 = f2lo(p0) + f2lo(p1) + dec_b[jj * 2];
                float v1 = f2hi(p0) + f2hi(p1) + dec_b[jj * 2 + 1];
                float* op = out + (size_t)(t - 1) * (B_ * NO) + b * NO + jj * 2;
                op[0] = v0; op[1] = v1;
            }
        }
        if (t == T_) {
            if (writeHidden) {
                for (int i = gid; i < B_ * NH; i += NTOT)
                    out[(size_t)T_ * B_ * NO + i] = __ldcg(g_hid[0] + i);
            }
            break;   // no trailing barrier needed
        }
        grid_barrier();
    }
}

// -----------------------------------------------------------------------------
extern "C" void kernel_launch(void* const* d_in, const int* in_sizes, int n_in,
                              void* d_out, int out_size) {
    const float* x       = (const float*)d_in[0];
    const float* enc_w   = (const float*)d_in[1];
    const float* enc_b   = (const float*)d_in[2];
    const float* rec_w   = (const float*)d_in[3];
    const float* fgt_w   = (const float*)d_in[4];
    const float* dec_w   = (const float*)d_in[5];
    const float* dec_b   = (const float*)d_in[6];
    const float* hinit_w = (const float*)d_in[7];
    const float* hinit_b = (const float*)d_in[8];
    float* out = (float*)d_out;

    init_hidden_kernel<<<(B_ * NH + 255) / 256, 256>>>(hinit_w, hinit_b);

    dim3 eg(T_ * B_ / 32, NH / 64);
    enc_kernel<<<eg, 256>>>(x, enc_w, enc_b);

    cudaFuncSetAttribute(persist_kernel, cudaFuncAttributeMaxDynamicSharedMemorySize,
                         SMEM_BYTES);
    int writeHidden = (out_size >= T_ * B_ * NO + B_ * NH) ? 1 : 0;
    persist_kernel<<<NCTA, NTHR, SMEM_BYTES>>>(rec_w, fgt_w, dec_w, dec_b, out, writeHidden);
}

// round 4
// speedup vs baseline: 1.1023x; 1.0204x over previous
#include <cuda_runtime.h>
#include <math.h>

#define B_   128
#define T_   512
#define NI   64
#define NH   1024
#define NO   64

#define NCTA    264          // 66 j-blocks * 2 b-split * 2 k-split
#define NTHR    128
#define KHALF   512
#define BK      32
#define NCHUNK  (KHALF/BK)   // 16
#define JTILE   16           // column-pairs per CTA
#define NPAIRID 132
#define SMEM_BYTES ((512*JTILE + 2*BK*64) * 8)   // 96 KB

// ---------------- scratch (device globals) -----------------------------------
__device__ float g_enc[(size_t)T_ * B_ * NH];
__device__ float g_hid[2][B_ * NH];
__device__ unsigned long long g_part[(size_t)NPAIRID * 2 * 8 * NTHR]; // [pair][kh][idx][tid]
__device__ unsigned g_flag[NPAIRID];
__device__ volatile unsigned g_gen;
__device__ unsigned g_cnt;

// ---------------- helpers -----------------------------------------------------
__device__ __forceinline__ float f2lo(unsigned long long v) { return __uint_as_float((unsigned)v); }
__device__ __forceinline__ float f2hi(unsigned long long v) { return __uint_as_float((unsigned)(v >> 32)); }
#define FMA2(d, a, b) asm("fma.rn.f32x2 %0, %1, %2, %0;" : "+l"(d) : "l"(a), "l"(b))

__device__ __forceinline__ unsigned long long ldcg_u64(const unsigned long long* p) {
    return __double_as_longlong(__ldcg((const double*)p));
}
__device__ __forceinline__ void stcg_u64(unsigned long long* p, unsigned long long v) {
    __stcg((double*)p, __longlong_as_double(v));
}

__device__ __forceinline__ void grid_barrier() {
    __threadfence();
    __syncthreads();
    if (threadIdx.x == 0) {
        unsigned gen = g_gen;
        if (atomicAdd(&g_cnt, 1) == NCTA - 1) {
            g_cnt = 0;
            __threadfence();
            g_gen = gen + 1;
        } else {
            while (g_gen == gen) __nanosleep(32);
        }
        __threadfence();
    }
    __syncthreads();
}

// ---------------- reset + init ------------------------------------------------
__global__ void reset_kernel() {
    int i = threadIdx.x;
    if (i == 0) { g_gen = 0; g_cnt = 0; }
    if (i < NPAIRID) g_flag[i] = 0;
}

__global__ void init_hidden_kernel(const float* __restrict__ hinit_w,
                                   const float* __restrict__ hinit_b) {
    int idx = blockIdx.x * blockDim.x + threadIdx.x;
    if (idx < B_ * NH) {
        int h = idx & (NH - 1);
        g_hid[0][idx] = hinit_w[h] + hinit_b[h];
    }
}

// ---------------- encoder GEMM (one-shot) -------------------------------------
__global__ void __launch_bounds__(256) enc_kernel(const float* __restrict__ x,
                                                  const float* __restrict__ enc_w,
                                                  const float* __restrict__ enc_b) {
    __shared__ float xs[32][NI + 1];
    __shared__ float ws[64][NI + 1];
    const int tid = threadIdx.x;
    const int tb0 = blockIdx.x * 32;
    const int h0  = blockIdx.y * 64;

    for (int i = tid; i < 32 * NI; i += 256) {
        int r = i >> 6, c = i & 63;
        int tb = tb0 + r;
        int t = tb >> 7, b = tb & 127;
        xs[r][c] = x[(size_t)b * (T_ * NI) + t * NI + c];
    }
    for (int i = tid; i < 64 * NI; i += 256) {
        int r = i >> 6, c = i & 63;
        ws[r][c] = enc_w[(h0 + r) * NI + c];
    }
    __syncthreads();

    const int rg = tid & 7;
    const int hg = tid >> 3;
    float acc[4][2] = {};
#pragma unroll
    for (int k = 0; k < NI; k++) {
        float w0 = ws[hg * 2 + 0][k];
        float w1 = ws[hg * 2 + 1][k];
#pragma unroll
        for (int j = 0; j < 4; j++) {
            float xv = xs[rg * 4 + j][k];
            acc[j][0] += xv * w0;
            acc[j][1] += xv * w1;
        }
    }
#pragma unroll
    for (int j = 0; j < 4; j++) {
        int tb = tb0 + rg * 4 + j;
#pragma unroll
        for (int q = 0; q < 2; q++) {
            int h = h0 + hg * 2 + q;
            g_enc[(size_t)tb * NH + h] = acc[j][q] + enc_b[h];
        }
    }
}

// ---------------- persistent recurrent kernel ----------------------------------
// bid: kh = bid&1 (k-half), bs = (bid>>1)&1 (b-half), jb = bid>>2 (0..65).
// pairid = bid>>1 : the two k-halves of the same (bs,jb).
// Column pair j: j<1024 -> (rec_w[j], fgt_w[j]); j>=1024 -> (dec_w[2(j-1024)], dec_w[2(j-1024)+1])
__global__ void __launch_bounds__(NTHR) persist_kernel(const float* __restrict__ rec_w,
                                                       const float* __restrict__ fgt_w,
                                                       const float* __restrict__ dec_w,
                                                       const float* __restrict__ dec_b,
                                                       float* __restrict__ out,
                                                       int writeHidden) {
    extern __shared__ float smem[];
    float2* ws  = (float2*)smem;                         // [512][16]
    float2* hsb = (float2*)(smem + 512 * JTILE * 2);     // [2][BK][64]

    const int tid    = threadIdx.x;
    const int bid    = blockIdx.x;
    const int kh     = bid & 1;
    const int pairid = bid >> 1;
    const int bs     = (bid >> 1) & 1;
    const int jb     = bid >> 2;
    const int j0     = jb * JTILE;
    const int b0     = bs * 64;

    const int hg = tid & 7;     // 8 j-groups of 2 pairs
    const int bg = tid >> 3;    // 16 b-groups of 4 rows

    // weight slice -> SMEM once
    for (int i = tid; i < 512 * JTILE; i += NTHR) {
        int k = i >> 4, jj = i & 15;
        int j = j0 + jj;
        int gk = kh * KHALF + k;
        float a, b;
        if (j < 1024) { a = rec_w[j * NH + gk]; b = fgt_w[j * NH + gk]; }
        else { int o = (j - 1024) * 2; a = dec_w[o * NH + gk]; b = dec_w[(o + 1) * NH + gk]; }
        ws[k * JTILE + jj] = make_float2(a, b);
    }
    __syncthreads();

    const size_t my_base   = (((size_t)pairid * 2 + kh) * 8) * NTHR + tid;
    const size_t peer_base = (((size_t)pairid * 2 + (kh ^ 1)) * 8) * NTHR + tid;

    for (int t = 0; t <= T_; t++) {
        const float* __restrict__ hin = g_hid[t & 1];
        const bool doGemm = (t < T_) || (jb >= 64);

        if (doGemm) {
            // ---------------- GEMM over this CTA's K-half ----------------
            float4 r[4];
#pragma unroll
            for (int s = 0; s < 4; s++) {
                int slot = s * NTHR + tid;
                int b = slot >> 3, kg = slot & 7;
                r[s] = __ldcg((const float4*)(hin + (b0 + b) * NH + kh * KHALF + kg * 4));
            }
            {
                float2* hb = hsb;
#pragma unroll
                for (int s = 0; s < 4; s++) {
                    int slot = s * NTHR + tid;
                    int b = slot >> 3, kg = slot & 7;
                    hb[(kg * 4 + 0) * 64 + b] = make_float2(r[s].x, r[s].x);
                    hb[(kg * 4 + 1) * 64 + b] = make_float2(r[s].y, r[s].y);
                    hb[(kg * 4 + 2) * 64 + b] = make_float2(r[s].z, r[s].z);
                    hb[(kg * 4 + 3) * 64 + b] = make_float2(r[s].w, r[s].w);
                }
            }
            __syncthreads();

            unsigned long long acc[4][2] = {};
            for (int kc = 0; kc < NCHUNK; kc++) {
                if (kc + 1 < NCHUNK) {
#pragma unroll
                    for (int s = 0; s < 4; s++) {
                        int slot = s * NTHR + tid;
                        int b = slot >> 3, kg = slot & 7;
                        r[s] = __ldcg((const float4*)(hin + (b0 + b) * NH + kh * KHALF +
                                                      (kc + 1) * BK + kg * 4));
                    }
                }
                const float2* hb = hsb + (kc & 1) * (BK * 64);
#pragma unroll
                for (int kk = 0; kk < BK; kk++) {
                    ulonglong2 ha = *(const ulonglong2*)(hb + kk * 64 + bg * 4);
                    ulonglong2 hc = *(const ulonglong2*)(hb + kk * 64 + bg * 4 + 2);
                    ulonglong2 wv = *(const ulonglong2*)(ws + (kc * BK + kk) * JTILE + hg * 2);
                    FMA2(acc[0][0], ha.x, wv.x); FMA2(acc[0][1], ha.x, wv.y);
                    FMA2(acc[1][0], ha.y, wv.x); FMA2(acc[1][1], ha.y, wv.y);
                    FMA2(acc[2][0], hc.x, wv.x); FMA2(acc[2][1], hc.x, wv.y);
                    FMA2(acc[3][0], hc.y, wv.x); FMA2(acc[3][1], hc.y, wv.y);
                }
                if (kc + 1 < NCHUNK) {
                    __syncthreads();
                    float2* hb2 = hsb + ((kc + 1) & 1) * (BK * 64);
#pragma unroll
                    for (int s = 0; s < 4; s++) {
                        int slot = s * NTHR + tid;
                        int b = slot >> 3, kg = slot & 7;
                        hb2[(kg * 4 + 0) * 64 + b] = make_float2(r[s].x, r[s].x);
                        hb2[(kg * 4 + 1) * 64 + b] = make_float2(r[s].y, r[s].y);
                        hb2[(kg * 4 + 2) * 64 + b] = make_float2(r[s].z, r[s].z);
                        hb2[(kg * 4 + 3) * 64 + b] = make_float2(r[s].w, r[s].w);
                    }
                    __syncthreads();
                }
            }

            // ---------------- publish partials, pair-local sync ----------------
#pragma unroll
            for (int idx = 0; idx < 8; idx++)
                stcg_u64(g_part + my_base + (size_t)idx * NTHR, acc[idx >> 1][idx & 1]);
            __threadfence();
            __syncthreads();
            if (tid == 0) {
                atomicAdd(&g_flag[pairid], 1u);
                unsigned target = 2u * (unsigned)(t + 1);
                while (((volatile unsigned*)g_flag)[pairid] < target) __nanosleep(32);
                __threadfence();
            }
            __syncthreads();

            // ---------------- combine + fused epilogue ----------------
            if (jb < 64) {
                const float* __restrict__ enc_t = g_enc + ((size_t)t << 17);
                float* __restrict__ hout = g_hid[(t + 1) & 1];
#pragma unroll
                for (int idx = 0; idx < 8; idx++) {
                    unsigned long long pv = ldcg_u64(g_part + peer_base + (size_t)idx * NTHR);
                    int ib = idx >> 1, jh = idx & 1;
                    float accR = f2lo(acc[ib][jh]) + f2lo(pv);
                    float accF = f2hi(acc[ib][jh]) + f2hi(pv);
                    int b = b0 + bg * 4 + ib;
                    int h = j0 + hg * 2 + jh;
                    float f = 1.0f / (1.0f + __expf(-accF));
                    float s = __ldcg(enc_t + b * NH + h) + accR;
                    float hnew = s / (1.0f + fabsf(s));
                    float hold = __ldcg(hin + b * NH + h);
                    __stcg(hout + b * NH + h, (1.0f - f) * hold + f * hnew);
                }
            } else if (t >= 1) {
                float* __restrict__ op = out + (size_t)(t - 1) * (B_ * NO);
#pragma unroll
                for (int idx = 0; idx < 8; idx++) {
                    unsigned long long pv = ldcg_u64(g_part + peer_base + (size_t)idx * NTHR);
                    int ib = idx >> 1, jh = idx & 1;
                    int b = b0 + bg * 4 + ib;
                    int o = (j0 + hg * 2 + jh - 1024) * 2;
                    float2 v;
                    v.x = f2lo(acc[ib][jh]) + f2lo(pv) + __ldg(dec_b + o);
                    v.y = f2hi(acc[ib][jh]) + f2hi(pv) + __ldg(dec_b + o + 1);
                    *(float2*)(op + b * NO + o) = v;
                }
            }
        }

        if (t == T_) {
            if (jb < 64 && writeHidden) {
                // bids 0..255 each copy 512 elements of final hidden
                int base = bid * (B_ * NH / 256);
                for (int i = tid; i < B_ * NH / 256; i += NTHR)
                    out[(size_t)T_ * B_ * NO + base + i] = __ldcg(&g_hid[0][base + i]);
            }
            break;
        }
        grid_barrier();
    }
}

// -------------------------------------------------------------------------------
extern "C" void kernel_launch(void* const* d_in, const int* in_sizes, int n_in,
                              void* d_out, int out_size) {
    const float* x       = (const float*)d_in[0];
    const float* enc_w   = (const float*)d_in[1];
    const float* enc_b   = (const float*)d_in[2];
    const float* rec_w   = (const float*)d_in[3];
    const float* fgt_w   = (const float*)d_in[4];
    const float* dec_w   = (const float*)d_in[5];
    const float* dec_b   = (const float*)d_in[6];
    const float* hinit_w = (const float*)d_in[7];
    const float* hinit_b = (const float*)d_in[8];
    float* out = (float*)d_out;

    reset_kernel<<<1, 256>>>();
    init_hidden_kernel<<<(B_ * NH + 255) / 256, 256>>>(hinit_w, hinit_b);

    dim3 eg(T_ * B_ / 32, NH / 64);
    enc_kernel<<<eg, 256>>>(x, enc_w, enc_b);

    cudaFuncSetAttribute(persist_kernel, cudaFuncAttributeMaxDynamicSharedMemorySize,
                         SMEM_BYTES);
    int writeHidden = (out_size >= T_ * B_ * NO + B_ * NH) ? 1 : 0;
    persist_kernel<<<NCTA, NTHR, SMEM_BYTES>>>(rec_w, fgt_w, dec_w, dec_b, out, writeHidden);
}

// round 6
// speedup vs baseline: 2.4010x; 2.1783x over previous
#include <cuda_runtime.h>
#include <math.h>

#define B_   128
#define T_   512
#define NI   64
#define NH   1024
#define NO   64

#define NJT    33            // 32 rec/fgt j-tiles + 1 dec j-tile
#define KSPLIT 8
#define NCTA   (NJT*KSPLIT)  // 264
#define NTHR   128
#define KSL    128           // k-slice per CTA
#define BK     16
#define NCHUNK (KSL/BK)      // 8
#define JP_CTA 32            // column-pairs per CTA
#define OUTS_CTA 4096        // 128 b * 32 pairs
#define SMEM_BYTES (32768 + 2*BK*B_*4)   // ws 32KB + hs 16KB = 48KB

// ---------------- scratch ------------------------------------------------------
__device__ float g_enc[(size_t)T_ * B_ * NH];          // [t][b][h]
__device__ float g_hidB[2][B_ * NH];                   // [b][h]
__device__ float g_hidT[2][NH * B_];                   // [h][b]
__device__ unsigned long long g_part[(size_t)NCTA * OUTS_CTA]; // [jt*8+ks][b*32+jp]
__device__ unsigned g_flag[NJT];
__device__ volatile unsigned g_gen;
__device__ unsigned g_cnt;

// ---------------- helpers ------------------------------------------------------
#define FMA2(d, a, b) asm("fma.rn.f32x2 %0, %1, %2, %0;" : "+l"(d) : "l"(a), "l"(b))
__device__ __forceinline__ unsigned long long dup2(float h) {
    unsigned long long r;
    asm("mov.b64 %0, {%1, %1};" : "=l"(r) : "f"(h));
    return r;
}

__device__ __forceinline__ void grid_barrier() {
    __threadfence();
    __syncthreads();
    if (threadIdx.x == 0) {
        unsigned gen = g_gen;
        if (atomicAdd(&g_cnt, 1) == NCTA - 1) {
            g_cnt = 0;
            __threadfence();
            g_gen = gen + 1;
        } else {
            while (g_gen == gen) __nanosleep(32);
        }
        __threadfence();
    }
    __syncthreads();
}

// ---------------- reset + init --------------------------------------------------
__global__ void reset_kernel() {
    int i = threadIdx.x;
    if (i == 0) { g_gen = 0; g_cnt = 0; }
    if (i < NJT) g_flag[i] = 0;
}

__global__ void init_hidden_kernel(const float* __restrict__ hinit_w,
                                   const float* __restrict__ hinit_b) {
    int idx = blockIdx.x * blockDim.x + threadIdx.x;
    if (idx < B_ * NH) {
        int hT = idx >> 7;                 // [h][b]
        g_hidT[0][idx] = hinit_w[hT] + hinit_b[hT];
        int hB = idx & (NH - 1);           // [b][h]
        g_hidB[0][idx] = hinit_w[hB] + hinit_b[hB];
    }
}

// ---------------- encoder GEMM (one-shot) ---------------------------------------
__global__ void __launch_bounds__(256) enc_kernel(const float* __restrict__ x,
                                                  const float* __restrict__ enc_w,
                                                  const float* __restrict__ enc_b) {
    __shared__ float xs[32][NI + 1];
    __shared__ float ws[64][NI + 1];
    const int tid = threadIdx.x;
    const int tb0 = blockIdx.x * 32;
    const int h0  = blockIdx.y * 64;

    for (int i = tid; i < 32 * NI; i += 256) {
        int r = i >> 6, c = i & 63;
        int tb = tb0 + r;
        int t = tb >> 7, b = tb & 127;
        xs[r][c] = x[(size_t)b * (T_ * NI) + t * NI + c];
    }
    for (int i = tid; i < 64 * NI; i += 256) {
        int r = i >> 6, c = i & 63;
        ws[r][c] = enc_w[(h0 + r) * NI + c];
    }
    __syncthreads();

    const int rg = tid & 7;
    const int hg = tid >> 3;
    float acc[4][2] = {};
#pragma unroll
    for (int k = 0; k < NI; k++) {
        float w0 = ws[hg * 2 + 0][k];
        float w1 = ws[hg * 2 + 1][k];
#pragma unroll
        for (int j = 0; j < 4; j++) {
            float xv = xs[rg * 4 + j][k];
            acc[j][0] += xv * w0;
            acc[j][1] += xv * w1;
        }
    }
#pragma unroll
    for (int j = 0; j < 4; j++) {
        int tb = tb0 + rg * 4 + j;
#pragma unroll
        for (int q = 0; q < 2; q++) {
            int h = h0 + hg * 2 + q;
            g_enc[(size_t)tb * NH + h] = acc[j][q] + enc_b[h];
        }
    }
}

// ---------------- persistent recurrent kernel ------------------------------------
// CTA: jt = bid>>3 (j-tile of 32 pairs), ks = bid&7 (k-slot of 128).
// Pair p = jt*32+jp: p<1024 -> (rec_w[p,:], fgt_w[p,:]); p>=1024 -> dec cols (2m,2m+1), m=p-1024.
__global__ void __launch_bounds__(NTHR) persist_kernel(const float* __restrict__ rec_w,
                                                       const float* __restrict__ fgt_w,
                                                       const float* __restrict__ dec_w,
                                                       const float* __restrict__ dec_b,
                                                       float* __restrict__ out,
                                                       int writeHidden) {
    extern __shared__ __align__(16) char smem[];
    unsigned long long* ws = (unsigned long long*)smem;     // [128 k][32 jp] (wA,wB)
    float* hsf = (float*)(smem + 32768);                    // [2][16 k][128 b]

    const int tid = threadIdx.x;
    const int bid = blockIdx.x;
    const int jt  = bid >> 3;        // 0..32
    const int ks  = bid & 7;         // 0..7
    const int j0  = jt * JP_CTA;     // global pair base
    const int kbase = ks * KSL;

    const int jg = tid & 7;          // 8 j-groups of 4 pairs
    const int bg = tid >> 3;         // 16 b-groups of 8 rows

    // ---- weights -> SMEM once ----
    for (int i = tid; i < KSL * JP_CTA; i += NTHR) {
        int k = i & (KSL - 1), jp = i >> 7;
        int p = j0 + jp;
        int gk = kbase + k;
        float a, b;
        if (p < 1024) { a = rec_w[p * NH + gk]; b = fgt_w[p * NH + gk]; }
        else { int m = p - 1024; a = dec_w[(2 * m) * NH + gk]; b = dec_w[(2 * m + 1) * NH + gk]; }
        ws[k * JP_CTA + jp] = ((unsigned long long)__float_as_uint(b) << 32) | __float_as_uint(a);
    }
    __syncthreads();

    // combine-phase identities
    const int bloc = ks * 16 + (tid >> 3);   // b this thread combines
    const int jpb  = (tid & 7) * 4;          // 4 consecutive jp
    float4 db0 = make_float4(0, 0, 0, 0), db1 = db0;
    if (jt == 32) {
        db0 = *(const float4*)(dec_b + jpb * 2);
        db1 = *(const float4*)(dec_b + jpb * 2 + 4);
    }

    unsigned long long* mypart = g_part + (size_t)bid * OUTS_CTA;

    for (int t = 0; t <= T_; t++) {
        const int cur = t & 1, nxt = (t + 1) & 1;
        const bool work = (t < T_) || (jt == 32);

        if (work) {
            // ================= GEMM over K-slice =================
            const float* __restrict__ hsrc = g_hidT[cur] + kbase * B_;
            float4 pf[4];
#pragma unroll
            for (int i = 0; i < 4; i++) {
                int slot = i * NTHR + tid;
                int row = slot >> 5, c4 = slot & 31;
                pf[i] = __ldcg((const float4*)(hsrc + row * B_ + c4 * 4));
            }
#pragma unroll
            for (int i = 0; i < 4; i++) {
                int slot = i * NTHR + tid;
                int row = slot >> 5, c4 = slot & 31;
                *(float4*)(hsf + row * B_ + c4 * 4) = pf[i];
            }

            ulonglong2 acc[8][2];
#pragma unroll
            for (int ib = 0; ib < 8; ib++)
#pragma unroll
                for (int jj = 0; jj < 2; jj++) { acc[ib][jj].x = 0ull; acc[ib][jj].y = 0ull; }

            for (int kc = 0; kc < NCHUNK; kc++) {
                if (kc + 1 < NCHUNK) {
#pragma unroll
                    for (int i = 0; i < 4; i++) {
                        int slot = i * NTHR + tid;
                        int row = slot >> 5, c4 = slot & 31;
                        pf[i] = __ldcg((const float4*)(hsrc + ((kc + 1) * BK + row) * B_ + c4 * 4));
                    }
                }
                __syncthreads();
                if (kc + 1 < NCHUNK) {
                    float* hb = hsf + ((kc + 1) & 1) * (BK * B_);
#pragma unroll
                    for (int i = 0; i < 4; i++) {
                        int slot = i * NTHR + tid;
                        int row = slot >> 5, c4 = slot & 31;
                        *(float4*)(hb + row * B_ + c4 * 4) = pf[i];
                    }
                }
                const float* hb = hsf + (kc & 1) * (BK * B_);
#pragma unroll
                for (int kk = 0; kk < BK; kk++) {
                    const float* hr = hb + kk * B_ + bg * 8;
                    float4 h0 = *(const float4*)hr;
                    float4 h1 = *(const float4*)(hr + 4);
                    const ulonglong2* wr = (const ulonglong2*)(ws + (kc * BK + kk) * JP_CTA + jg * 4);
                    ulonglong2 w0 = wr[0];
                    ulonglong2 w1 = wr[1];
                    unsigned long long d0 = dup2(h0.x), d1 = dup2(h0.y), d2 = dup2(h0.z), d3 = dup2(h0.w);
                    unsigned long long d4 = dup2(h1.x), d5 = dup2(h1.y), d6 = dup2(h1.z), d7 = dup2(h1.w);
                    FMA2(acc[0][0].x, d0, w0.x); FMA2(acc[0][0].y, d0, w0.y); FMA2(acc[0][1].x, d0, w1.x); FMA2(acc[0][1].y, d0, w1.y);
                    FMA2(acc[1][0].x, d1, w0.x); FMA2(acc[1][0].y, d1, w0.y); FMA2(acc[1][1].x, d1, w1.x); FMA2(acc[1][1].y, d1, w1.y);
                    FMA2(acc[2][0].x, d2, w0.x); FMA2(acc[2][0].y, d2, w0.y); FMA2(acc[2][1].x, d2, w1.x); FMA2(acc[2][1].y, d2, w1.y);
                    FMA2(acc[3][0].x, d3, w0.x); FMA2(acc[3][0].y, d3, w0.y); FMA2(acc[3][1].x, d3, w1.x); FMA2(acc[3][1].y, d3, w1.y);
                    FMA2(acc[4][0].x, d4, w0.x); FMA2(acc[4][0].y, d4, w0.y); FMA2(acc[4][1].x, d4, w1.x); FMA2(acc[4][1].y, d4, w1.y);
                    FMA2(acc[5][0].x, d5, w0.x); FMA2(acc[5][0].y, d5, w0.y); FMA2(acc[5][1].x, d5, w1.x); FMA2(acc[5][1].y, d5, w1.y);
                    FMA2(acc[6][0].x, d6, w0.x); FMA2(acc[6][0].y, d6, w0.y); FMA2(acc[6][1].x, d6, w1.x); FMA2(acc[6][1].y, d6, w1.y);
                    FMA2(acc[7][0].x, d7, w0.x); FMA2(acc[7][0].y, d7, w0.y); FMA2(acc[7][1].x, d7, w1.x); FMA2(acc[7][1].y, d7, w1.y);
                }
            }

            // ---- publish partials: [b][jp] as ulonglong2 (coalesced) ----
#pragma unroll
            for (int ib = 0; ib < 8; ib++) {
                int b = bg * 8 + ib;
#pragma unroll
                for (int jj = 0; jj < 2; jj++)
                    *(ulonglong2*)(mypart + b * JP_CTA + jg * 4 + jj * 2) = acc[ib][jj];
            }
            __threadfence();
            __syncthreads();
            if (tid == 0) {
                atomicAdd(&g_flag[jt], 1u);
                unsigned target = 8u * (unsigned)(t + 1);
                while (((volatile unsigned*)g_flag)[jt] < target) __nanosleep(32);
                __threadfence();
            }
            __syncthreads();

            // ---- combine 8 k-slots + fused epilogue ----
            float R[4] = {0, 0, 0, 0}, F[4] = {0, 0, 0, 0};
            const unsigned long long* gp = g_part + (size_t)(jt * KSPLIT) * OUTS_CTA + bloc * JP_CTA + jpb;
#pragma unroll
            for (int k2 = 0; k2 < KSPLIT; k2++) {
                uint4 q0 = __ldcg((const uint4*)(gp + (size_t)k2 * OUTS_CTA));
                uint4 q1 = __ldcg((const uint4*)(gp + (size_t)k2 * OUTS_CTA + 2));
                R[0] += __uint_as_float(q0.x); F[0] += __uint_as_float(q0.y);
                R[1] += __uint_as_float(q0.z); F[1] += __uint_as_float(q0.w);
                R[2] += __uint_as_float(q1.x); F[2] += __uint_as_float(q1.y);
                R[3] += __uint_as_float(q1.z); F[3] += __uint_as_float(q1.w);
            }

            if (jt < 32) {
                int hg0 = j0 + jpb;
                float4 e  = __ldcg((const float4*)(g_enc + (size_t)t * (B_ * NH) + bloc * NH + hg0));
                float4 ho = __ldcg((const float4*)(g_hidB[cur] + bloc * NH + hg0));
                float hv[4];
                const float ev[4] = {e.x, e.y, e.z, e.w};
                const float hov[4] = {ho.x, ho.y, ho.z, ho.w};
#pragma unroll
                for (int i = 0; i < 4; i++) {
                    float f = 1.0f / (1.0f + __expf(-F[i]));
                    float s = ev[i] + R[i];
                    float hn = s / (1.0f + fabsf(s));
                    hv[i] = (1.0f - f) * hov[i] + f * hn;
                }
                *(float4*)(g_hidB[nxt] + bloc * NH + hg0) = make_float4(hv[0], hv[1], hv[2], hv[3]);
#pragma unroll
                for (int i = 0; i < 4; i++)
                    g_hidT[nxt][(hg0 + i) * B_ + bloc] = hv[i];
            } else if (t >= 1) {
                float4 v0 = make_float4(R[0] + db0.x, F[0] + db0.y, R[1] + db0.z, F[1] + db0.w);
                float4 v1 = make_float4(R[2] + db1.x, F[2] + db1.y, R[3] + db1.z, F[3] + db1.w);
                float* op = out + (size_t)(t - 1) * (B_ * NO) + bloc * NO + jpb * 2;
                *(float4*)op = v0;
                *(float4*)(op + 4) = v1;
            }
        }

        if (t == T_) break;
        grid_barrier();
    }

    // final hidden copy (after out[T-1] has been written by dec CTAs)
    if (writeHidden && jt < 32) {
        int rid = jt * 8 + ks;               // 0..255, each copies 512 floats
        const float* src = g_hidB[0] + rid * 512;
        float* dst = out + (size_t)T_ * B_ * NO + rid * 512;
        *(float4*)(dst + tid * 4) = __ldcg((const float4*)(src + tid * 4));
    }
}

// --------------------------------------------------------------------------------
extern "C" void kernel_launch(void* const* d_in, const int* in_sizes, int n_in,
                              void* d_out, int out_size) {
    const float* x       = (const float*)d_in[0];
    const float* enc_w   = (const float*)d_in[1];
    const float* enc_b   = (const float*)d_in[2];
    const float* rec_w   = (const float*)d_in[3];
    const float* fgt_w   = (const float*)d_in[4];
    const float* dec_w   = (const float*)d_in[5];
    const float* dec_b   = (const float*)d_in[6];
    const float* hinit_w = (const float*)d_in[7];
    const float* hinit_b = (const float*)d_in[8];
    float* out = (float*)d_out;

    reset_kernel<<<1, 64>>>();
    init_hidden_kernel<<<(B_ * NH + 255) / 256, 256>>>(hinit_w, hinit_b);

    dim3 eg(T_ * B_ / 32, NH / 64);
    enc_kernel<<<eg, 256>>>(x, enc_w, enc_b);

    cudaFuncSetAttribute(persist_kernel, cudaFuncAttributeMaxDynamicSharedMemorySize,
                         SMEM_BYTES);
    int writeHidden = (out_size >= T_ * B_ * NO + B_ * NH) ? 1 : 0;
    persist_kernel<<<NCTA, NTHR, SMEM_BYTES>>>(rec_w, fgt_w, dec_w, dec_b, out, writeHidden);
}